// round 1
// baseline (speedup 1.0000x reference)
#include <cuda_runtime.h>

// Problem constants
#define T_STEPS 16
#define B_SZ    4096
#define D_SZ    512
#define M_SZ    (T_STEPS * B_SZ)      // 65536 rows of the GEMM
#define PLANE   (B_SZ * D_SZ)         // 2097152 elements per timestep

// GEMM tiling
#define BM 128
#define BN 128
#define BK 16
#define TM 8
#define TN 8
#define MTILES (M_SZ / BM)            // 512
#define NTILES (D_SZ / BN)            // 4

// Scratch (static __device__ arrays — allocation-free per harness rules)
__device__ float g_y[(size_t)M_SZ * D_SZ];          // 134 MB GEMM output
__device__ float g_psum[MTILES * D_SZ];             // per-M-tile partial sums
__device__ float g_psq[MTILES * D_SZ];              // per-M-tile partial sum-of-squares
__device__ float g_scale[D_SZ];                     // gamma * rstd
__device__ float g_shift[D_SZ];                     // beta - mean * gamma * rstd

// ---------------------------------------------------------------------------
// Kernel 1: y[m][n] = sum_k X[m][k] * W[n][k]   (bias cancels inside BN)
// Also emits deterministic per-CTA BN partial stats (sum, sum of squares).
// ---------------------------------------------------------------------------
__global__ __launch_bounds__(256, 1)
void gemm_stats_kernel(const float* __restrict__ X, const float* __restrict__ W) {
    __shared__ float As[BK][BM + 4];
    __shared__ float Bs[BK][BN + 4];

    const int bn = blockIdx.x * BN;     // feature tile
    const int bm = blockIdx.y * BM;     // row tile
    const int tid = threadIdx.x;
    const int trow = tid >> 4;          // 0..15
    const int tcol = tid & 15;          // 0..15

    float acc[TM][TN];
    #pragma unroll
    for (int i = 0; i < TM; i++)
        #pragma unroll
        for (int j = 0; j < TN; j++) acc[i][j] = 0.f;

    // loader mapping: 256 threads load 128 rows x 16 cols (A and B)
    const int lrow = tid >> 2;            // 0..63
    const int lc4  = (tid & 3) * 4;       // 0,4,8,12

    const float* Xb = X + (size_t)bm * D_SZ;
    const float* Wb = W + (size_t)bn * D_SZ;

    for (int kt = 0; kt < D_SZ; kt += BK) {
        #pragma unroll
        for (int h = 0; h < 2; h++) {
            int r = lrow + 64 * h;
            float4 va = *(const float4*)(Xb + (size_t)r * D_SZ + kt + lc4);
            As[lc4 + 0][r] = va.x; As[lc4 + 1][r] = va.y;
            As[lc4 + 2][r] = va.z; As[lc4 + 3][r] = va.w;
            float4 vb = *(const float4*)(Wb + (size_t)r * D_SZ + kt + lc4);
            Bs[lc4 + 0][r] = vb.x; Bs[lc4 + 1][r] = vb.y;
            Bs[lc4 + 2][r] = vb.z; Bs[lc4 + 3][r] = vb.w;
        }
        __syncthreads();

        #pragma unroll
        for (int k = 0; k < BK; k++) {
            float ra[TM], rb[TN];
            #pragma unroll
            for (int i = 0; i < TM; i++) ra[i] = As[k][trow * TM + i];
            #pragma unroll
            for (int j = 0; j < TN; j++) rb[j] = Bs[k][tcol * TN + j];
            #pragma unroll
            for (int i = 0; i < TM; i++)
                #pragma unroll
                for (int j = 0; j < TN; j++)
                    acc[i][j] = fmaf(ra[i], rb[j], acc[i][j]);
        }
        __syncthreads();
    }

    // write y tile (vectorized)
    {
        const size_t orow0 = (size_t)(bm + trow * TM);
        const int    ocol0 = bn + tcol * TN;
        #pragma unroll
        for (int i = 0; i < TM; i++) {
            float4 v0 = make_float4(acc[i][0], acc[i][1], acc[i][2], acc[i][3]);
            float4 v1 = make_float4(acc[i][4], acc[i][5], acc[i][6], acc[i][7]);
            float* p = g_y + (orow0 + i) * D_SZ + ocol0;
            *(float4*)(p)     = v0;
            *(float4*)(p + 4) = v1;
        }
    }

    // BN partial stats: reduce the 128-row tile per feature column.
    // Reuse As/Bs as reduction scratch (safe: k-loop ended with __syncthreads).
    float* redS = &As[0][0];   // 16 x 128
    float* redQ = &Bs[0][0];
    #pragma unroll
    for (int j = 0; j < TN; j++) {
        float s = 0.f, q = 0.f;
        #pragma unroll
        for (int i = 0; i < TM; i++) { float a = acc[i][j]; s += a; q += a * a; }
        redS[trow * BN + tcol * TN + j] = s;
        redQ[trow * BN + tcol * TN + j] = q;
    }
    __syncthreads();
    if (tid < BN) {
        float s = 0.f, q = 0.f;
        #pragma unroll
        for (int r = 0; r < 16; r++) {
            s += redS[r * BN + tid];
            q += redQ[r * BN + tid];
        }
        // Deterministic (no atomics): each (m-tile, feature) slot written once.
        g_psum[blockIdx.y * D_SZ + bn + tid] = s;
        g_psq [blockIdx.y * D_SZ + bn + tid] = q;
    }
}

// ---------------------------------------------------------------------------
// Kernel 2: finalize BN stats -> per-feature scale/shift
// ---------------------------------------------------------------------------
__global__ void finalize_kernel(const float* __restrict__ gamma,
                                const float* __restrict__ beta) {
    int d = threadIdx.x;   // 512 threads, 1 block
    float s = 0.f, q = 0.f;
    for (int r = 0; r < MTILES; r++) {
        s += g_psum[r * D_SZ + d];
        q += g_psq [r * D_SZ + d];
    }
    const float inv_n = 1.0f / (float)M_SZ;
    float mean = s * inv_n;
    float var  = q * inv_n - mean * mean;
    float rstd = rsqrtf(var + 1e-5f);
    float sc = gamma[d] * rstd;
    g_scale[d] = sc;
    g_shift[d] = beta[d] - mean * sc;
}

// ---------------------------------------------------------------------------
// Kernel 3: BN apply + residual + LIF scan over T, one thread per (b, d)
// ---------------------------------------------------------------------------
__global__ __launch_bounds__(256)
void lif_kernel(const float* __restrict__ x, float* __restrict__ out) {
    const int idx = blockIdx.x * blockDim.x + threadIdx.x;   // 0 .. PLANE-1
    const int d = idx & (D_SZ - 1);
    const float sc = g_scale[d];
    const float sh = g_shift[d];

    float v = 0.f;
    #pragma unroll
    for (int t = 0; t < T_STEPS; t++) {
        const size_t off = (size_t)t * PLANE + idx;
        float h   = fmaf(g_y[off], sc, sh);
        float inp = h + x[off];
        v = v + (inp - v) * 0.5f;          // tau = 2, same order as reference
        bool fire = (v >= 1.0f);
        out[off] = fire ? 1.0f : 0.0f;
        v = fire ? 0.0f : v;               // hard reset
    }
}

// ---------------------------------------------------------------------------
// launch
// ---------------------------------------------------------------------------
extern "C" void kernel_launch(void* const* d_in, const int* in_sizes, int n_in,
                              void* d_out, int out_size) {
    const float* x_seq = (const float*)d_in[0];   // [T,B,D]
    const float* W     = (const float*)d_in[1];   // [D,D]
    // d_in[2] = b : mathematically cancels inside BatchNorm -> unused
    const float* gamma = (const float*)d_in[3];
    const float* beta  = (const float*)d_in[4];
    float* out = (float*)d_out;

    dim3 ggrid(NTILES, MTILES);
    gemm_stats_kernel<<<ggrid, 256>>>(x_seq, W);
    finalize_kernel<<<1, D_SZ>>>(gamma, beta);
    lif_kernel<<<PLANE / 256, 256>>>(x_seq, out);
}

// round 4
// speedup vs baseline: 1.8428x; 1.8428x over previous
#include <cuda_runtime.h>
#include <cuda_fp16.h>
#include <cstdint>

// ---------------- problem constants ----------------
#define T_STEPS 16
#define B_SZ    4096
#define D_SZ    512
#define M_SZ    (T_STEPS * B_SZ)      // 65536
#define PLANE   (B_SZ * D_SZ)

// ---------------- GEMM tiling ----------------
#define BM 128
#define BN 128
#define BK 32
#define KITERS (D_SZ / BK)            // 16
#define MTILES (M_SZ / BM)            // 512
#define NTILES (D_SZ / BN)            // 4

#define PADK 40                                   // halves per SMEM row (bank-conflict-free)
#define TILE_H (BM * PADK)                        // halves per tile
#define TILE_BYTES (TILE_H * 2)                   // 10240 B
#define STAGE_BYTES (4 * TILE_BYTES)              // Ah, Al, Bh, Bl = 40960 B
#define DYN_SMEM (2 * STAGE_BYTES)                // 81920 B

// ---------------- scratch ----------------
__device__ float g_y[(size_t)M_SZ * D_SZ];
__device__ float g_psum[MTILES * D_SZ];
__device__ float g_psq [MTILES * D_SZ];
__device__ float g_scale[D_SZ];
__device__ float g_shift[D_SZ];

// ---------------- helpers ----------------
__device__ __forceinline__ uint32_t pack_h2(half a, half b) {
    __half2 h = __halves2half2(a, b);
    return *(uint32_t*)&h;
}

// split one float4 into hi (fp16) and lo (fp16 of residual), packed as uint2
__device__ __forceinline__ void split4(float4 v, uint2& hi, uint2& lo) {
    half hx = __float2half_rn(v.x), hy = __float2half_rn(v.y);
    half hz = __float2half_rn(v.z), hw = __float2half_rn(v.w);
    float lx = v.x - __half2float(hx), ly = v.y - __half2float(hy);
    float lz = v.z - __half2float(hz), lw = v.w - __half2float(hw);
    hi.x = pack_h2(hx, hy);
    hi.y = pack_h2(hz, hw);
    lo.x = pack_h2(__float2half_rn(lx), __float2half_rn(ly));
    lo.y = pack_h2(__float2half_rn(lz), __float2half_rn(lw));
}

__device__ __forceinline__ void mma16816(float* c, const uint32_t* a, const uint32_t* b) {
    asm volatile(
        "mma.sync.aligned.m16n8k16.row.col.f32.f16.f16.f32 "
        "{%0,%1,%2,%3}, {%4,%5,%6,%7}, {%8,%9}, {%0,%1,%2,%3};"
        : "+f"(c[0]), "+f"(c[1]), "+f"(c[2]), "+f"(c[3])
        : "r"(a[0]), "r"(a[1]), "r"(a[2]), "r"(a[3]), "r"(b[0]), "r"(b[1]));
}

// ---------------------------------------------------------------------------
// fp16x3 split-precision GEMM on tensor cores (mma.sync):
//   y = X * W^T, plus deterministic per-CTA BN partial stats.
// ---------------------------------------------------------------------------
__global__ __launch_bounds__(256, 1)
void gemm_mma_kernel(const float* __restrict__ X, const float* __restrict__ W) {
    extern __shared__ char dsm[];

    const int tid  = threadIdx.x;
    const int lane = tid & 31;
    const int warp = tid >> 5;
    const int wm   = warp >> 2;        // 0..1  (64-row slab)
    const int wn   = warp & 3;         // 0..3  (32-col slab)
    const int bm = blockIdx.y * BM;
    const int bn = blockIdx.x * BN;

    // loader mapping: thread -> (row, 16-col half)
    const int lr = tid >> 1;           // 0..127
    const int lc = (tid & 1) * 16;     // 0 or 16
    const float* xr = X + (size_t)(bm + lr) * D_SZ + lc;
    const float* wr = W + (size_t)(bn + lr) * D_SZ + lc;

    float acc[4][4][4];
    #pragma unroll
    for (int i = 0; i < 4; i++)
        #pragma unroll
        for (int j = 0; j < 4; j++)
            #pragma unroll
            for (int r = 0; r < 4; r++) acc[i][j][r] = 0.f;

    float4 px[4], pw[4];
    #pragma unroll
    for (int g = 0; g < 4; g++) {
        px[g] = *(const float4*)(xr + g * 4);
        pw[g] = *(const float4*)(wr + g * 4);
    }

    #pragma unroll 1
    for (int it = 0; it < KITERS; ++it) {
        const int buf = it & 1;
        half* Ah = (half*)(dsm + buf * STAGE_BYTES);
        half* Al = Ah + TILE_H;
        half* Bh = Al + TILE_H;
        half* Bl = Bh + TILE_H;

        // split current prefetch into SMEM
        #pragma unroll
        for (int g = 0; g < 4; g++) {
            uint2 hi, lo;
            split4(px[g], hi, lo);
            *(uint2*)(Ah + lr * PADK + lc + g * 4) = hi;
            *(uint2*)(Al + lr * PADK + lc + g * 4) = lo;
            split4(pw[g], hi, lo);
            *(uint2*)(Bh + lr * PADK + lc + g * 4) = hi;
            *(uint2*)(Bl + lr * PADK + lc + g * 4) = lo;
        }
        __syncthreads();

        // prefetch next k-slice while MMAs run
        if (it + 1 < KITERS) {
            const int kt = (it + 1) * BK;
            #pragma unroll
            for (int g = 0; g < 4; g++) {
                px[g] = *(const float4*)(xr + kt + g * 4);
                pw[g] = *(const float4*)(wr + kt + g * 4);
            }
        }

        // MMA over the two k16 chunks of this BK=32 slice
        #pragma unroll
        for (int ch = 0; ch < 2; ch++) {
            const int col = ch * 16 + (lane & 3) * 2;
            uint32_t ah[4][4], al[4][4], bh[4][2], bl[4][2];
            #pragma unroll
            for (int mi = 0; mi < 4; mi++) {
                const int r0 = wm * 64 + mi * 16 + (lane >> 2);
                ah[mi][0] = *(const uint32_t*)(Ah + r0 * PADK + col);
                ah[mi][1] = *(const uint32_t*)(Ah + (r0 + 8) * PADK + col);
                ah[mi][2] = *(const uint32_t*)(Ah + r0 * PADK + col + 8);
                ah[mi][3] = *(const uint32_t*)(Ah + (r0 + 8) * PADK + col + 8);
                al[mi][0] = *(const uint32_t*)(Al + r0 * PADK + col);
                al[mi][1] = *(const uint32_t*)(Al + (r0 + 8) * PADK + col);
                al[mi][2] = *(const uint32_t*)(Al + r0 * PADK + col + 8);
                al[mi][3] = *(const uint32_t*)(Al + (r0 + 8) * PADK + col + 8);
            }
            #pragma unroll
            for (int nj = 0; nj < 4; nj++) {
                const int rn = wn * 32 + nj * 8 + (lane >> 2);
                bh[nj][0] = *(const uint32_t*)(Bh + rn * PADK + col);
                bh[nj][1] = *(const uint32_t*)(Bh + rn * PADK + col + 8);
                bl[nj][0] = *(const uint32_t*)(Bl + rn * PADK + col);
                bl[nj][1] = *(const uint32_t*)(Bl + rn * PADK + col + 8);
            }
            #pragma unroll
            for (int mi = 0; mi < 4; mi++)
                #pragma unroll
                for (int nj = 0; nj < 4; nj++) {
                    mma16816(acc[mi][nj], ah[mi], bh[nj]);   // hi*hi
                    mma16816(acc[mi][nj], ah[mi], bl[nj]);   // hi*lo
                    mma16816(acc[mi][nj], al[mi], bh[nj]);   // lo*hi
                }
        }
        // single sync per iter: next store targets the other buffer; by the
        // time any warp reaches the store for buffer b again it has passed
        // this iteration's sync, which orders all LDS reads of buffer b.
    }
    __syncthreads();

    // ---------------- epilogue: y store + BN partials ----------------
    const int qrow = lane >> 2;              // 0..7
    const int qcol = (lane & 3) * 2;         // 0,2,4,6
    #pragma unroll
    for (int mi = 0; mi < 4; mi++) {
        #pragma unroll
        for (int nj = 0; nj < 4; nj++) {
            const size_t r0 = (size_t)(bm + wm * 64 + mi * 16 + qrow);
            const int    c0 = bn + wn * 32 + nj * 8 + qcol;
            *(float2*)(g_y + r0 * D_SZ + c0) =
                make_float2(acc[mi][nj][0], acc[mi][nj][1]);
            *(float2*)(g_y + (r0 + 8) * D_SZ + c0) =
                make_float2(acc[mi][nj][2], acc[mi][nj][3]);
        }
    }

    // deterministic BN partial reduction via SMEM slots (alias stage memory)
    float* red_s = (float*)dsm;                    // 128 cols x 16 slots
    float* red_q = red_s + 128 * 16;
    #pragma unroll
    for (int nj = 0; nj < 4; nj++) {
        #pragma unroll
        for (int par = 0; par < 2; par++) {
            float s = 0.f, q = 0.f;
            #pragma unroll
            for (int mi = 0; mi < 4; mi++) {
                float a0 = acc[mi][nj][par];       // row r
                float a1 = acc[mi][nj][2 + par];   // row r+8
                s += a0 + a1;
                q += a0 * a0 + a1 * a1;
            }
            const int c    = wn * 32 + nj * 8 + qcol + par;   // 0..127
            const int slot = wm * 8 + qrow;                    // 0..15
            red_s[c * 16 + slot] = s;
            red_q[c * 16 + slot] = q;
        }
    }
    __syncthreads();
    if (tid < 128) {
        float s = 0.f, q = 0.f;
        #pragma unroll
        for (int k = 0; k < 16; k++) {
            s += red_s[tid * 16 + k];
            q += red_q[tid * 16 + k];
        }
        g_psum[blockIdx.y * D_SZ + bn + tid] = s;
        g_psq [blockIdx.y * D_SZ + bn + tid] = q;
    }
}

// ---------------------------------------------------------------------------
// finalize BN stats -> per-feature scale/shift (one block per feature)
// ---------------------------------------------------------------------------
__global__ void finalize_kernel(const float* __restrict__ gamma,
                                const float* __restrict__ beta) {
    const int d = blockIdx.x;
    const int t = threadIdx.x;       // 128
    float s = 0.f, q = 0.f;
    #pragma unroll 4
    for (int r = t; r < MTILES; r += 128) {
        s += g_psum[r * D_SZ + d];
        q += g_psq [r * D_SZ + d];
    }
    #pragma unroll
    for (int o = 16; o; o >>= 1) {
        s += __shfl_xor_sync(0xffffffffu, s, o);
        q += __shfl_xor_sync(0xffffffffu, q, o);
    }
    __shared__ float ss[4], sq[4];
    if ((t & 31) == 0) { ss[t >> 5] = s; sq[t >> 5] = q; }
    __syncthreads();
    if (t == 0) {
        float S = ss[0] + ss[1] + ss[2] + ss[3];
        float Q = sq[0] + sq[1] + sq[2] + sq[3];
        const float inv_n = 1.0f / (float)M_SZ;
        float mean = S * inv_n;
        float var  = Q * inv_n - mean * mean;
        float rstd = rsqrtf(var + 1e-5f);
        float sc = gamma[d] * rstd;
        g_scale[d] = sc;
        g_shift[d] = beta[d] - mean * sc;
    }
}

// ---------------------------------------------------------------------------
// BN apply + residual + LIF scan (vectorized float4)
// ---------------------------------------------------------------------------
__global__ __launch_bounds__(256)
void lif_kernel(const float* __restrict__ x, float* __restrict__ out) {
    const int i4 = blockIdx.x * blockDim.x + threadIdx.x;  // float4 index in a plane
    const int d4 = (i4 & 127) * 4;
    const float4 sc = *(const float4*)(g_scale + d4);
    const float4 sh = *(const float4*)(g_shift + d4);
    const float4* yp = (const float4*)g_y;
    const float4* xp = (const float4*)x;
    float4*       op = (float4*)out;

    float4 v = make_float4(0.f, 0.f, 0.f, 0.f);
    #pragma unroll
    for (int t = 0; t < T_STEPS; t++) {
        const size_t off = (size_t)t * (PLANE / 4) + i4;
        float4 y = yp[off];
        float4 xv = xp[off];
        float4 o;
        {
            float h = fmaf(y.x, sc.x, sh.x) + xv.x;
            v.x = v.x + (h - v.x) * 0.5f;
            bool f = (v.x >= 1.0f); o.x = f ? 1.f : 0.f; v.x = f ? 0.f : v.x;
        }
        {
            float h = fmaf(y.y, sc.y, sh.y) + xv.y;
            v.y = v.y + (h - v.y) * 0.5f;
            bool f = (v.y >= 1.0f); o.y = f ? 1.f : 0.f; v.y = f ? 0.f : v.y;
        }
        {
            float h = fmaf(y.z, sc.z, sh.z) + xv.z;
            v.z = v.z + (h - v.z) * 0.5f;
            bool f = (v.z >= 1.0f); o.z = f ? 1.f : 0.f; v.z = f ? 0.f : v.z;
        }
        {
            float h = fmaf(y.w, sc.w, sh.w) + xv.w;
            v.w = v.w + (h - v.w) * 0.5f;
            bool f = (v.w >= 1.0f); o.w = f ? 1.f : 0.f; v.w = f ? 0.f : v.w;
        }
        op[off] = o;
    }
}

// ---------------------------------------------------------------------------
extern "C" void kernel_launch(void* const* d_in, const int* in_sizes, int n_in,
                              void* d_out, int out_size) {
    const float* x_seq = (const float*)d_in[0];   // [T,B,D]
    const float* W     = (const float*)d_in[1];   // [D,D]
    // d_in[2] = b : cancels inside BatchNorm
    const float* gamma = (const float*)d_in[3];
    const float* beta  = (const float*)d_in[4];
    float* out = (float*)d_out;

    cudaFuncSetAttribute(gemm_mma_kernel,
                         cudaFuncAttributeMaxDynamicSharedMemorySize, DYN_SMEM);

    dim3 ggrid(NTILES, MTILES);
    gemm_mma_kernel<<<ggrid, 256, DYN_SMEM>>>(x_seq, W);
    finalize_kernel<<<D_SZ, 128>>>(gamma, beta);
    lif_kernel<<<(PLANE / 4) / 256, 256>>>(x_seq, out);
}

// round 5
// speedup vs baseline: 2.1529x; 1.1683x over previous
#include <cuda_runtime.h>
#include <cuda_fp16.h>
#include <cstdint>

// ---------------- problem constants ----------------
#define T_STEPS 16
#define B_SZ    4096
#define D_SZ    512
#define M_SZ    (T_STEPS * B_SZ)      // 65536
#define PLANE   (B_SZ * D_SZ)

// ---------------- GEMM tiling ----------------
#define BM 128
#define BN 128
#define BK 32
#define KITERS (D_SZ / BK)            // 16
#define MTILES (M_SZ / BM)            // 512
#define NTILES (D_SZ / BN)            // 4
#define NSTAGE 3

#define TILE_BYTES  (BM * BK * 2)     // 8192 B (fp16 tile, 64B rows, SW64 swizzle)
#define STAGE_BYTES (4 * TILE_BYTES)  // Ah, Al, Bh, Bl = 32768 B
#define DYN_SMEM    (NSTAGE * STAGE_BYTES)   // 98304 B

// ---------------- scratch ----------------
__device__ float  g_y[(size_t)M_SZ * D_SZ];
__device__ __half g_Xh[(size_t)M_SZ * D_SZ];
__device__ __half g_Xl[(size_t)M_SZ * D_SZ];
__device__ __half g_Wh[D_SZ * D_SZ];
__device__ __half g_Wl[D_SZ * D_SZ];
__device__ float  g_psum[MTILES * D_SZ];
__device__ float  g_psq [MTILES * D_SZ];
__device__ float  g_scale[D_SZ];
__device__ float  g_shift[D_SZ];

// ---------------- PTX helpers ----------------
__device__ __forceinline__ uint32_t smem_u32(const void* p) {
    uint32_t a;
    asm("{ .reg .u64 t; cvta.to.shared.u64 t, %1; cvt.u32.u64 %0, t; }"
        : "=r"(a) : "l"(p));
    return a;
}

#define CP_ASYNC16(dst, src) \
    asm volatile("cp.async.cg.shared.global [%0], [%1], 16;" :: "r"(dst), "l"(src))
#define CP_COMMIT() asm volatile("cp.async.commit_group;")
#define CP_WAIT2()  asm volatile("cp.async.wait_group 2;")

#define LDSM_X4(r0, r1, r2, r3, addr) \
    asm volatile("ldmatrix.sync.aligned.m8n8.x4.shared.b16 {%0,%1,%2,%3}, [%4];" \
        : "=r"(r0), "=r"(r1), "=r"(r2), "=r"(r3) : "r"(addr))

__device__ __forceinline__ void mma16816(float* c, const uint32_t* a,
                                         uint32_t b0, uint32_t b1) {
    asm volatile(
        "mma.sync.aligned.m16n8k16.row.col.f32.f16.f16.f32 "
        "{%0,%1,%2,%3}, {%4,%5,%6,%7}, {%8,%9}, {%0,%1,%2,%3};"
        : "+f"(c[0]), "+f"(c[1]), "+f"(c[2]), "+f"(c[3])
        : "r"(a[0]), "r"(a[1]), "r"(a[2]), "r"(a[3]), "r"(b0), "r"(b1));
}

// ---------------------------------------------------------------------------
// split kernels: fp32 -> (hi fp16, lo fp16 residual)
// ---------------------------------------------------------------------------
__device__ __forceinline__ void split8(const float4 a, const float4 b,
                                       uint4& hi, uint4& lo) {
    half h0 = __float2half_rn(a.x), h1 = __float2half_rn(a.y);
    half h2 = __float2half_rn(a.z), h3 = __float2half_rn(a.w);
    half h4 = __float2half_rn(b.x), h5 = __float2half_rn(b.y);
    half h6 = __float2half_rn(b.z), h7 = __float2half_rn(b.w);
    __half2 p0 = __halves2half2(h0, h1), p1 = __halves2half2(h2, h3);
    __half2 p2 = __halves2half2(h4, h5), p3 = __halves2half2(h6, h7);
    hi = make_uint4(*(uint32_t*)&p0, *(uint32_t*)&p1,
                    *(uint32_t*)&p2, *(uint32_t*)&p3);
    __half2 q0 = __halves2half2(__float2half_rn(a.x - __half2float(h0)),
                                __float2half_rn(a.y - __half2float(h1)));
    __half2 q1 = __halves2half2(__float2half_rn(a.z - __half2float(h2)),
                                __float2half_rn(a.w - __half2float(h3)));
    __half2 q2 = __halves2half2(__float2half_rn(b.x - __half2float(h4)),
                                __float2half_rn(b.y - __half2float(h5)));
    __half2 q3 = __halves2half2(__float2half_rn(b.z - __half2float(h6)),
                                __float2half_rn(b.w - __half2float(h7)));
    lo = make_uint4(*(uint32_t*)&q0, *(uint32_t*)&q1,
                    *(uint32_t*)&q2, *(uint32_t*)&q3);
}

__global__ __launch_bounds__(256)
void split_x_kernel(const float* __restrict__ X) {
    const size_t i = (size_t)(blockIdx.x * blockDim.x + threadIdx.x) * 8;
    float4 a = *(const float4*)(X + i);
    float4 b = *(const float4*)(X + i + 4);
    uint4 hi, lo;
    split8(a, b, hi, lo);
    *(uint4*)((char*)g_Xh + i * 2) = hi;
    *(uint4*)((char*)g_Xl + i * 2) = lo;
}

__global__ __launch_bounds__(256)
void split_w_kernel(const float* __restrict__ W) {
    const size_t i = (size_t)(blockIdx.x * blockDim.x + threadIdx.x) * 8;
    float4 a = *(const float4*)(W + i);
    float4 b = *(const float4*)(W + i + 4);
    uint4 hi, lo;
    split8(a, b, hi, lo);
    *(uint4*)((char*)g_Wh + i * 2) = hi;
    *(uint4*)((char*)g_Wl + i * 2) = lo;
}

// ---------------------------------------------------------------------------
// fp16x3 tensor-core GEMM with cp.async + ldmatrix + deterministic BN partials
// ---------------------------------------------------------------------------
__global__ __launch_bounds__(256, 2)
void gemm_mma_kernel() {
    extern __shared__ char dsm[];

    const int tid  = threadIdx.x;
    const int lane = tid & 31;
    const int warp = tid >> 5;
    const int wm   = warp >> 2;        // 0..1 (64-row slab)
    const int wn   = warp & 3;         // 0..3 (32-col slab)
    const int bm = blockIdx.y * BM;
    const int bn = blockIdx.x * BN;

    const uint32_t smem_base = smem_u32(dsm);

    // ---- loader mapping: thread -> (row, 32B chunk pair) ----
    const int lrow  = tid >> 1;          // 0..127
    const int lc16  = (tid & 1) * 2;     // 16B-chunk index 0 or 2
    const __half* pXh = g_Xh + (size_t)(bm + lrow) * D_SZ + lc16 * 8;
    const __half* pXl = g_Xl + (size_t)(bm + lrow) * D_SZ + lc16 * 8;
    const __half* pWh = g_Wh + (size_t)(bn + lrow) * D_SZ + lc16 * 8;
    const __half* pWl = g_Wl + (size_t)(bn + lrow) * D_SZ + lc16 * 8;
    uint32_t so;
    {
        uint32_t o = (uint32_t)(lrow * 64 + lc16 * 16);
        so = o ^ ((o >> 3) & 0x30);      // SW64 swizzle
    }
    const uint32_t so2 = so ^ 16;

    // ---- fragment lane offsets (swizzled, lane-constant) ----
    // A: row_off = (lane&7) + bit3(lane)*8 ; colb = (lane>>4)*16
    uint32_t alo[2];
    {
        uint32_t row_off = (lane & 7) + ((lane >> 3) & 1) * 8;
        uint32_t colb = (lane >> 4) * 16;
        #pragma unroll
        for (int ch = 0; ch < 2; ch++) {
            uint32_t o = row_off * 64 + ch * 32 + colb;
            alo[ch] = o ^ (((row_off & 6)) << 3);
        }
    }
    // B: row = lane&7 ; hi tile for lanes<16, lo tile for lanes>=16 ;
    //    colb = bit3(lane)*16
    uint32_t blo[2];
    {
        uint32_t row_b = lane & 7;
        uint32_t colb = ((lane >> 3) & 1) * 16;
        uint32_t tsel = (lane < 16) ? 0u : (uint32_t)TILE_BYTES;
        #pragma unroll
        for (int ch = 0; ch < 2; ch++) {
            uint32_t o = row_b * 64 + ch * 32 + colb;
            blo[ch] = (o ^ ((row_b & 6) << 3)) + tsel;
        }
    }

    float acc[4][4][4];
    #pragma unroll
    for (int i = 0; i < 4; i++)
        #pragma unroll
        for (int j = 0; j < 4; j++)
            #pragma unroll
            for (int r = 0; r < 4; r++) acc[i][j][r] = 0.f;

    // ---- stage issue helper ----
    auto issue_stage = [&](int stg) {
        const uint32_t sb = smem_base + (stg % NSTAGE) * STAGE_BYTES;
        const int kt = stg * BK;
        CP_ASYNC16(sb + so,                    pXh + kt);
        CP_ASYNC16(sb + so2,                   pXh + kt + 8);
        CP_ASYNC16(sb + TILE_BYTES + so,       pXl + kt);
        CP_ASYNC16(sb + TILE_BYTES + so2,      pXl + kt + 8);
        CP_ASYNC16(sb + 2 * TILE_BYTES + so,   pWh + kt);
        CP_ASYNC16(sb + 2 * TILE_BYTES + so2,  pWh + kt + 8);
        CP_ASYNC16(sb + 3 * TILE_BYTES + so,   pWl + kt);
        CP_ASYNC16(sb + 3 * TILE_BYTES + so2,  pWl + kt + 8);
    };

    issue_stage(0); CP_COMMIT();
    issue_stage(1); CP_COMMIT();
    issue_stage(2); CP_COMMIT();

    #pragma unroll 1
    for (int it = 0; it < KITERS; ++it) {
        CP_WAIT2();
        __syncthreads();

        const uint32_t sb  = smem_base + (it % NSTAGE) * STAGE_BYTES;
        const uint32_t sAh = sb + wm * 4096;
        const uint32_t sAl = sAh + TILE_BYTES;
        const uint32_t sB  = sb + 2 * TILE_BYTES + wn * 2048;  // +blo picks Bh/Bl

        #pragma unroll
        for (int ch = 0; ch < 2; ch++) {
            uint32_t ah[4][4], al[4][4];
            #pragma unroll
            for (int mi = 0; mi < 4; mi++) {
                LDSM_X4(ah[mi][0], ah[mi][1], ah[mi][2], ah[mi][3],
                        sAh + mi * 1024 + alo[ch]);
                LDSM_X4(al[mi][0], al[mi][1], al[mi][2], al[mi][3],
                        sAl + mi * 1024 + alo[ch]);
            }
            #pragma unroll
            for (int nj = 0; nj < 4; nj++) {
                uint32_t b0, b1, b2, b3;   // Bh c, Bh c+8, Bl c, Bl c+8
                LDSM_X4(b0, b1, b2, b3, sB + nj * 512 + blo[ch]);
                #pragma unroll
                for (int mi = 0; mi < 4; mi++) {
                    mma16816(acc[mi][nj], ah[mi], b0, b1);   // hi*hi
                    mma16816(acc[mi][nj], ah[mi], b2, b3);   // hi*lo
                    mma16816(acc[mi][nj], al[mi], b0, b1);   // lo*hi
                }
            }
        }
        __syncthreads();
        if (it + NSTAGE < KITERS) issue_stage(it + NSTAGE);
        CP_COMMIT();   // empty group in tail iters keeps wait_group math valid
    }

    // ---------------- epilogue: y store + BN partials ----------------
    const int qrow = lane >> 2;              // 0..7
    const int qcol = (lane & 3) * 2;         // 0,2,4,6
    #pragma unroll
    for (int mi = 0; mi < 4; mi++) {
        #pragma unroll
        for (int nj = 0; nj < 4; nj++) {
            const size_t r0 = (size_t)(bm + wm * 64 + mi * 16 + qrow);
            const int    c0 = bn + wn * 32 + nj * 8 + qcol;
            *(float2*)(g_y + r0 * D_SZ + c0) =
                make_float2(acc[mi][nj][0], acc[mi][nj][1]);
            *(float2*)(g_y + (r0 + 8) * D_SZ + c0) =
                make_float2(acc[mi][nj][2], acc[mi][nj][3]);
        }
    }

    // deterministic BN partial reduction via SMEM slots (alias stage memory)
    float* red_s = (float*)dsm;                    // 128 cols x 16 slots
    float* red_q = red_s + 128 * 16;
    #pragma unroll
    for (int nj = 0; nj < 4; nj++) {
        #pragma unroll
        for (int par = 0; par < 2; par++) {
            float s = 0.f, q = 0.f;
            #pragma unroll
            for (int mi = 0; mi < 4; mi++) {
                float a0 = acc[mi][nj][par];
                float a1 = acc[mi][nj][2 + par];
                s += a0 + a1;
                q += a0 * a0 + a1 * a1;
            }
            const int c    = wn * 32 + nj * 8 + qcol + par;   // 0..127
            const int slot = wm * 8 + qrow;                    // 0..15
            red_s[c * 16 + slot] = s;
            red_q[c * 16 + slot] = q;
        }
    }
    __syncthreads();
    if (tid < 128) {
        float s = 0.f, q = 0.f;
        #pragma unroll
        for (int k = 0; k < 16; k++) {
            s += red_s[tid * 16 + k];
            q += red_q[tid * 16 + k];
        }
        g_psum[blockIdx.y * D_SZ + bn + tid] = s;
        g_psq [blockIdx.y * D_SZ + bn + tid] = q;
    }
}

// ---------------------------------------------------------------------------
// finalize BN stats -> per-feature scale/shift (one block per feature)
// ---------------------------------------------------------------------------
__global__ void finalize_kernel(const float* __restrict__ gamma,
                                const float* __restrict__ beta) {
    const int d = blockIdx.x;
    const int t = threadIdx.x;       // 128
    float s = 0.f, q = 0.f;
    #pragma unroll 4
    for (int r = t; r < MTILES; r += 128) {
        s += g_psum[r * D_SZ + d];
        q += g_psq [r * D_SZ + d];
    }
    #pragma unroll
    for (int o = 16; o; o >>= 1) {
        s += __shfl_xor_sync(0xffffffffu, s, o);
        q += __shfl_xor_sync(0xffffffffu, q, o);
    }
    __shared__ float ss[4], sq[4];
    if ((t & 31) == 0) { ss[t >> 5] = s; sq[t >> 5] = q; }
    __syncthreads();
    if (t == 0) {
        float S = ss[0] + ss[1] + ss[2] + ss[3];
        float Q = sq[0] + sq[1] + sq[2] + sq[3];
        const float inv_n = 1.0f / (float)M_SZ;
        float mean = S * inv_n;
        float var  = Q * inv_n - mean * mean;
        float rstd = rsqrtf(var + 1e-5f);
        float sc = gamma[d] * rstd;
        g_scale[d] = sc;
        g_shift[d] = beta[d] - mean * sc;
    }
}

// ---------------------------------------------------------------------------
// BN apply + residual + LIF scan (vectorized float4)
// ---------------------------------------------------------------------------
__global__ __launch_bounds__(256)
void lif_kernel(const float* __restrict__ x, float* __restrict__ out) {
    const int i4 = blockIdx.x * blockDim.x + threadIdx.x;
    const int d4 = (i4 & 127) * 4;
    const float4 sc = *(const float4*)(g_scale + d4);
    const float4 sh = *(const float4*)(g_shift + d4);
    const float4* yp = (const float4*)g_y;
    const float4* xp = (const float4*)x;
    float4*       op = (float4*)out;

    float4 v = make_float4(0.f, 0.f, 0.f, 0.f);
    #pragma unroll
    for (int t = 0; t < T_STEPS; t++) {
        const size_t off = (size_t)t * (PLANE / 4) + i4;
        float4 y = yp[off];
        float4 xv = xp[off];
        float4 o;
        {
            float h = fmaf(y.x, sc.x, sh.x) + xv.x;
            v.x = v.x + (h - v.x) * 0.5f;
            bool f = (v.x >= 1.0f); o.x = f ? 1.f : 0.f; v.x = f ? 0.f : v.x;
        }
        {
            float h = fmaf(y.y, sc.y, sh.y) + xv.y;
            v.y = v.y + (h - v.y) * 0.5f;
            bool f = (v.y >= 1.0f); o.y = f ? 1.f : 0.f; v.y = f ? 0.f : v.y;
        }
        {
            float h = fmaf(y.z, sc.z, sh.z) + xv.z;
            v.z = v.z + (h - v.z) * 0.5f;
            bool f = (v.z >= 1.0f); o.z = f ? 1.f : 0.f; v.z = f ? 0.f : v.z;
        }
        {
            float h = fmaf(y.w, sc.w, sh.w) + xv.w;
            v.w = v.w + (h - v.w) * 0.5f;
            bool f = (v.w >= 1.0f); o.w = f ? 1.f : 0.f; v.w = f ? 0.f : v.w;
        }
        op[off] = o;
    }
}

// ---------------------------------------------------------------------------
extern "C" void kernel_launch(void* const* d_in, const int* in_sizes, int n_in,
                              void* d_out, int out_size) {
    const float* x_seq = (const float*)d_in[0];   // [T,B,D]
    const float* W     = (const float*)d_in[1];   // [D,D]
    // d_in[2] = b : cancels inside BatchNorm
    const float* gamma = (const float*)d_in[3];
    const float* beta  = (const float*)d_in[4];
    float* out = (float*)d_out;

    cudaFuncSetAttribute(gemm_mma_kernel,
                         cudaFuncAttributeMaxDynamicSharedMemorySize, DYN_SMEM);

    split_x_kernel<<<((size_t)M_SZ * D_SZ / 8) / 256, 256>>>(x_seq);
    split_w_kernel<<<(D_SZ * D_SZ / 8) / 256, 256>>>(W);

    dim3 ggrid(NTILES, MTILES);
    gemm_mma_kernel<<<ggrid, 256, DYN_SMEM>>>();
    finalize_kernel<<<D_SZ, 128>>>(gamma, beta);
    lif_kernel<<<(PLANE / 4) / 256, 256>>>(x_seq, out);
}

// round 6
// speedup vs baseline: 2.1567x; 1.0018x over previous
#include <cuda_runtime.h>
#include <cuda_fp16.h>
#include <cstdint>

// ---------------- problem constants ----------------
#define T_STEPS 16
#define B_SZ    4096
#define D_SZ    512
#define M_SZ    (T_STEPS * B_SZ)      // 65536
#define PLANE   (B_SZ * D_SZ)

// ---------------- GEMM tiling ----------------
#define BM 128
#define BN 128
#define BK 32
#define KITERS (D_SZ / BK)            // 16
#define MTILES (M_SZ / BM)            // 512
#define NTILES (D_SZ / BN)            // 4
#define NSTAGE 3

#define TILE_BYTES  (BM * BK * 2)     // 8192 B (fp16 tile, 64B rows, SW64 swizzle)
#define STAGE_BYTES (4 * TILE_BYTES)  // Ah, Al, Bh, Bl = 32768 B
#define DYN_SMEM    (NSTAGE * STAGE_BYTES)   // 98304 B

// ---------------- scratch ----------------
__device__ float  g_y[(size_t)M_SZ * D_SZ];
__device__ __half g_Xh[(size_t)M_SZ * D_SZ];
__device__ __half g_Xl[(size_t)M_SZ * D_SZ];
__device__ __half g_Wh[D_SZ * D_SZ];
__device__ __half g_Wl[D_SZ * D_SZ];
__device__ float  g_psum[MTILES * D_SZ];
__device__ float  g_psq [MTILES * D_SZ];
__device__ float  g_scale[D_SZ];
__device__ float  g_shift[D_SZ];

// ---------------- PTX helpers ----------------
__device__ __forceinline__ uint32_t smem_u32(const void* p) {
    uint32_t a;
    asm("{ .reg .u64 t; cvta.to.shared.u64 t, %1; cvt.u32.u64 %0, t; }"
        : "=r"(a) : "l"(p));
    return a;
}

#define CP_ASYNC16(dst, src) \
    asm volatile("cp.async.cg.shared.global [%0], [%1], 16;" :: "r"(dst), "l"(src))
#define CP_COMMIT() asm volatile("cp.async.commit_group;")
#define CP_WAIT1()  asm volatile("cp.async.wait_group 1;")

#define LDSM_X4(r0, r1, r2, r3, addr) \
    asm volatile("ldmatrix.sync.aligned.m8n8.x4.shared.b16 {%0,%1,%2,%3}, [%4];" \
        : "=r"(r0), "=r"(r1), "=r"(r2), "=r"(r3) : "r"(addr))

__device__ __forceinline__ void mma16816(float* c, const uint32_t* a,
                                         uint32_t b0, uint32_t b1) {
    asm volatile(
        "mma.sync.aligned.m16n8k16.row.col.f32.f16.f16.f32 "
        "{%0,%1,%2,%3}, {%4,%5,%6,%7}, {%8,%9}, {%0,%1,%2,%3};"
        : "+f"(c[0]), "+f"(c[1]), "+f"(c[2]), "+f"(c[3])
        : "r"(a[0]), "r"(a[1]), "r"(a[2]), "r"(a[3]), "r"(b0), "r"(b1));
}

// ---------------------------------------------------------------------------
// split kernel: fp32 -> (hi fp16, lo fp16 residual) for X and W in one launch
// ---------------------------------------------------------------------------
__device__ __forceinline__ void split8(const float4 a, const float4 b,
                                       uint4& hi, uint4& lo) {
    half h0 = __float2half_rn(a.x), h1 = __float2half_rn(a.y);
    half h2 = __float2half_rn(a.z), h3 = __float2half_rn(a.w);
    half h4 = __float2half_rn(b.x), h5 = __float2half_rn(b.y);
    half h6 = __float2half_rn(b.z), h7 = __float2half_rn(b.w);
    __half2 p0 = __halves2half2(h0, h1), p1 = __halves2half2(h2, h3);
    __half2 p2 = __halves2half2(h4, h5), p3 = __halves2half2(h6, h7);
    hi = make_uint4(*(uint32_t*)&p0, *(uint32_t*)&p1,
                    *(uint32_t*)&p2, *(uint32_t*)&p3);
    __half2 q0 = __halves2half2(__float2half_rn(a.x - __half2float(h0)),
                                __float2half_rn(a.y - __half2float(h1)));
    __half2 q1 = __halves2half2(__float2half_rn(a.z - __half2float(h2)),
                                __float2half_rn(a.w - __half2float(h3)));
    __half2 q2 = __halves2half2(__float2half_rn(b.x - __half2float(h4)),
                                __float2half_rn(b.y - __half2float(h5)));
    __half2 q3 = __halves2half2(__float2half_rn(b.z - __half2float(h6)),
                                __float2half_rn(b.w - __half2float(h7)));
    lo = make_uint4(*(uint32_t*)&q0, *(uint32_t*)&q1,
                    *(uint32_t*)&q2, *(uint32_t*)&q3);
}

#define XBLKS ((size_t)M_SZ * D_SZ / 8 / 256)     // 16384
#define WBLKS ((size_t)D_SZ * D_SZ / 8 / 256)     // 128

__global__ __launch_bounds__(256)
void split_kernel(const float* __restrict__ X, const float* __restrict__ W) {
    if (blockIdx.x < XBLKS) {
        const size_t i = (size_t)(blockIdx.x * 256 + threadIdx.x) * 8;
        float4 a = *(const float4*)(X + i);
        float4 b = *(const float4*)(X + i + 4);
        uint4 hi, lo;
        split8(a, b, hi, lo);
        *(uint4*)((char*)g_Xh + i * 2) = hi;
        *(uint4*)((char*)g_Xl + i * 2) = lo;
    } else {
        const size_t i = (size_t)((blockIdx.x - XBLKS) * 256 + threadIdx.x) * 8;
        float4 a = *(const float4*)(W + i);
        float4 b = *(const float4*)(W + i + 4);
        uint4 hi, lo;
        split8(a, b, hi, lo);
        *(uint4*)((char*)g_Wh + i * 2) = hi;
        *(uint4*)((char*)g_Wl + i * 2) = lo;
    }
}

// ---------------------------------------------------------------------------
// fp16x3 tensor-core GEMM: cp.async pipeline, ldmatrix, product-major MMAs,
// deterministic BN partials.
// ---------------------------------------------------------------------------
__global__ __launch_bounds__(256, 2)
void gemm_mma_kernel() {
    extern __shared__ char dsm[];

    const int tid  = threadIdx.x;
    const int lane = tid & 31;
    const int warp = tid >> 5;
    const int wm   = warp >> 2;        // 0..1 (64-row slab)
    const int wn   = warp & 3;         // 0..3 (32-col slab)
    const int bm = blockIdx.y * BM;
    const int bn = blockIdx.x * BN;

    const uint32_t smem_base = smem_u32(dsm);

    // ---- loader mapping: thread -> (row, 32B chunk pair) ----
    const int lrow  = tid >> 1;          // 0..127
    const int lc16  = (tid & 1) * 2;     // 16B-chunk index 0 or 2
    const __half* pXh = g_Xh + (size_t)(bm + lrow) * D_SZ + lc16 * 8;
    const __half* pXl = g_Xl + (size_t)(bm + lrow) * D_SZ + lc16 * 8;
    const __half* pWh = g_Wh + (size_t)(bn + lrow) * D_SZ + lc16 * 8;
    const __half* pWl = g_Wl + (size_t)(bn + lrow) * D_SZ + lc16 * 8;
    uint32_t so;
    {
        uint32_t o = (uint32_t)(lrow * 64 + lc16 * 16);
        so = o ^ ((o >> 3) & 0x30);      // SW64 swizzle
    }
    const uint32_t so2 = so ^ 16;

    // ---- fragment lane offsets (swizzled, lane-constant) ----
    uint32_t alo[2];
    {
        uint32_t row_off = (lane & 7) + ((lane >> 3) & 1) * 8;
        uint32_t colb = (lane >> 4) * 16;
        #pragma unroll
        for (int ch = 0; ch < 2; ch++) {
            uint32_t o = row_off * 64 + ch * 32 + colb;
            alo[ch] = o ^ (((row_off & 6)) << 3);
        }
    }
    uint32_t blo[2];
    {
        uint32_t row_b = lane & 7;
        uint32_t colb = ((lane >> 3) & 1) * 16;
        uint32_t tsel = (lane < 16) ? 0u : (uint32_t)TILE_BYTES;
        #pragma unroll
        for (int ch = 0; ch < 2; ch++) {
            uint32_t o = row_b * 64 + ch * 32 + colb;
            blo[ch] = (o ^ ((row_b & 6) << 3)) + tsel;
        }
    }

    float acc[4][4][4];
    #pragma unroll
    for (int i = 0; i < 4; i++)
        #pragma unroll
        for (int j = 0; j < 4; j++)
            #pragma unroll
            for (int r = 0; r < 4; r++) acc[i][j][r] = 0.f;

    auto issue_stage = [&](int stg) {
        const uint32_t sb = smem_base + (stg % NSTAGE) * STAGE_BYTES;
        const int kt = stg * BK;
        CP_ASYNC16(sb + so,                    pXh + kt);
        CP_ASYNC16(sb + so2,                   pXh + kt + 8);
        CP_ASYNC16(sb + TILE_BYTES + so,       pXl + kt);
        CP_ASYNC16(sb + TILE_BYTES + so2,      pXl + kt + 8);
        CP_ASYNC16(sb + 2 * TILE_BYTES + so,   pWh + kt);
        CP_ASYNC16(sb + 2 * TILE_BYTES + so2,  pWh + kt + 8);
        CP_ASYNC16(sb + 3 * TILE_BYTES + so,   pWl + kt);
        CP_ASYNC16(sb + 3 * TILE_BYTES + so2,  pWl + kt + 8);
    };

    issue_stage(0); CP_COMMIT();
    issue_stage(1); CP_COMMIT();

    #pragma unroll 1
    for (int it = 0; it < KITERS; ++it) {
        CP_WAIT1();                 // stage `it` resident
        __syncthreads();            // visibility of all threads' cp.asyncs;
                                    // also proves stage it-1's slot is free

        if (it + 2 < KITERS) issue_stage(it + 2);
        CP_COMMIT();                // (empty group in tail keeps count valid)

        const uint32_t sb  = smem_base + (it % NSTAGE) * STAGE_BYTES;
        const uint32_t sAh = sb + wm * 4096;
        const uint32_t sAl = sAh + TILE_BYTES;
        const uint32_t sB  = sb + 2 * TILE_BYTES + wn * 2048;

        #pragma unroll
        for (int ch = 0; ch < 2; ch++) {
            uint32_t ah[4][4], al[4][4], bh[4][2], bl[4][2];
            #pragma unroll
            for (int mi = 0; mi < 4; mi++) {
                LDSM_X4(ah[mi][0], ah[mi][1], ah[mi][2], ah[mi][3],
                        sAh + mi * 1024 + alo[ch]);
                LDSM_X4(al[mi][0], al[mi][1], al[mi][2], al[mi][3],
                        sAl + mi * 1024 + alo[ch]);
            }
            #pragma unroll
            for (int nj = 0; nj < 4; nj++)
                LDSM_X4(bh[nj][0], bh[nj][1], bl[nj][0], bl[nj][1],
                        sB + nj * 512 + blo[ch]);

            // product-major: dependent reuses of any acc are 16 issues apart.
            // Per-accumulator order is still hh, hl, lh -> bitwise identical.
            #pragma unroll
            for (int mi = 0; mi < 4; mi++)
                #pragma unroll
                for (int nj = 0; nj < 4; nj++)
                    mma16816(acc[mi][nj], ah[mi], bh[nj][0], bh[nj][1]);
            #pragma unroll
            for (int mi = 0; mi < 4; mi++)
                #pragma unroll
                for (int nj = 0; nj < 4; nj++)
                    mma16816(acc[mi][nj], ah[mi], bl[nj][0], bl[nj][1]);
            #pragma unroll
            for (int mi = 0; mi < 4; mi++)
                #pragma unroll
                for (int nj = 0; nj < 4; nj++)
                    mma16816(acc[mi][nj], al[mi], bh[nj][0], bh[nj][1]);
        }
        // no second barrier: next iter's top barrier protects slot reuse
    }
    __syncthreads();

    // ---------------- epilogue: y store + BN partials ----------------
    const int qrow = lane >> 2;              // 0..7
    const int qcol = (lane & 3) * 2;         // 0,2,4,6
    #pragma unroll
    for (int mi = 0; mi < 4; mi++) {
        #pragma unroll
        for (int nj = 0; nj < 4; nj++) {
            const size_t r0 = (size_t)(bm + wm * 64 + mi * 16 + qrow);
            const int    c0 = bn + wn * 32 + nj * 8 + qcol;
            *(float2*)(g_y + r0 * D_SZ + c0) =
                make_float2(acc[mi][nj][0], acc[mi][nj][1]);
            *(float2*)(g_y + (r0 + 8) * D_SZ + c0) =
                make_float2(acc[mi][nj][2], acc[mi][nj][3]);
        }
    }

    float* red_s = (float*)dsm;                    // 128 cols x 16 slots
    float* red_q = red_s + 128 * 16;
    #pragma unroll
    for (int nj = 0; nj < 4; nj++) {
        #pragma unroll
        for (int par = 0; par < 2; par++) {
            float s = 0.f, q = 0.f;
            #pragma unroll
            for (int mi = 0; mi < 4; mi++) {
                float a0 = acc[mi][nj][par];
                float a1 = acc[mi][nj][2 + par];
                s += a0 + a1;
                q += a0 * a0 + a1 * a1;
            }
            const int c    = wn * 32 + nj * 8 + qcol + par;   // 0..127
            const int slot = wm * 8 + qrow;                    // 0..15
            red_s[c * 16 + slot] = s;
            red_q[c * 16 + slot] = q;
        }
    }
    __syncthreads();
    if (tid < 128) {
        float s = 0.f, q = 0.f;
        #pragma unroll
        for (int k = 0; k < 16; k++) {
            s += red_s[tid * 16 + k];
            q += red_q[tid * 16 + k];
        }
        g_psum[blockIdx.y * D_SZ + bn + tid] = s;
        g_psq [blockIdx.y * D_SZ + bn + tid] = q;
    }
}

// ---------------------------------------------------------------------------
// finalize BN stats -> per-feature scale/shift (one block per feature)
// ---------------------------------------------------------------------------
__global__ void finalize_kernel(const float* __restrict__ gamma,
                                const float* __restrict__ beta) {
    const int d = blockIdx.x;
    const int t = threadIdx.x;       // 128
    float s = 0.f, q = 0.f;
    #pragma unroll 4
    for (int r = t; r < MTILES; r += 128) {
        s += g_psum[r * D_SZ + d];
        q += g_psq [r * D_SZ + d];
    }
    #pragma unroll
    for (int o = 16; o; o >>= 1) {
        s += __shfl_xor_sync(0xffffffffu, s, o);
        q += __shfl_xor_sync(0xffffffffu, q, o);
    }
    __shared__ float ss[4], sq[4];
    if ((t & 31) == 0) { ss[t >> 5] = s; sq[t >> 5] = q; }
    __syncthreads();
    if (t == 0) {
        float S = ss[0] + ss[1] + ss[2] + ss[3];
        float Q = sq[0] + sq[1] + sq[2] + sq[3];
        const float inv_n = 1.0f / (float)M_SZ;
        float mean = S * inv_n;
        float var  = Q * inv_n - mean * mean;
        float rstd = rsqrtf(var + 1e-5f);
        float sc = gamma[d] * rstd;
        g_scale[d] = sc;
        g_shift[d] = beta[d] - mean * sc;
    }
}

// ---------------------------------------------------------------------------
// BN apply + residual + LIF scan (vectorized float4)
// ---------------------------------------------------------------------------
__global__ __launch_bounds__(256)
void lif_kernel(const float* __restrict__ x, float* __restrict__ out) {
    const int i4 = blockIdx.x * blockDim.x + threadIdx.x;
    const int d4 = (i4 & 127) * 4;
    const float4 sc = *(const float4*)(g_scale + d4);
    const float4 sh = *(const float4*)(g_shift + d4);
    const float4* yp = (const float4*)g_y;
    const float4* xp = (const float4*)x;
    float4*       op = (float4*)out;

    float4 v = make_float4(0.f, 0.f, 0.f, 0.f);
    #pragma unroll
    for (int t = 0; t < T_STEPS; t++) {
        const size_t off = (size_t)t * (PLANE / 4) + i4;
        float4 y = yp[off];
        float4 xv = xp[off];
        float4 o;
        {
            float h = fmaf(y.x, sc.x, sh.x) + xv.x;
            v.x = v.x + (h - v.x) * 0.5f;
            bool f = (v.x >= 1.0f); o.x = f ? 1.f : 0.f; v.x = f ? 0.f : v.x;
        }
        {
            float h = fmaf(y.y, sc.y, sh.y) + xv.y;
            v.y = v.y + (h - v.y) * 0.5f;
            bool f = (v.y >= 1.0f); o.y = f ? 1.f : 0.f; v.y = f ? 0.f : v.y;
        }
        {
            float h = fmaf(y.z, sc.z, sh.z) + xv.z;
            v.z = v.z + (h - v.z) * 0.5f;
            bool f = (v.z >= 1.0f); o.z = f ? 1.f : 0.f; v.z = f ? 0.f : v.z;
        }
        {
            float h = fmaf(y.w, sc.w, sh.w) + xv.w;
            v.w = v.w + (h - v.w) * 0.5f;
            bool f = (v.w >= 1.0f); o.w = f ? 1.f : 0.f; v.w = f ? 0.f : v.w;
        }
        op[off] = o;
    }
}

// ---------------------------------------------------------------------------
extern "C" void kernel_launch(void* const* d_in, const int* in_sizes, int n_in,
                              void* d_out, int out_size) {
    const float* x_seq = (const float*)d_in[0];   // [T,B,D]
    const float* W     = (const float*)d_in[1];   // [D,D]
    // d_in[2] = b : cancels inside BatchNorm
    const float* gamma = (const float*)d_in[3];
    const float* beta  = (const float*)d_in[4];
    float* out = (float*)d_out;

    cudaFuncSetAttribute(gemm_mma_kernel,
                         cudaFuncAttributeMaxDynamicSharedMemorySize, DYN_SMEM);

    split_kernel<<<(unsigned)(XBLKS + WBLKS), 256>>>(x_seq, W);

    dim3 ggrid(NTILES, MTILES);
    gemm_mma_kernel<<<ggrid, 256, DYN_SMEM>>>();
    finalize_kernel<<<D_SZ, 128>>>(gamma, beta);
    lif_kernel<<<(PLANE / 4) / 256, 256>>>(x_seq, out);
}